// round 1
// baseline (speedup 1.0000x reference)
#include <cuda_runtime.h>

// One CTA per segment. Pass 1: block-reduce sum of |y| over the segment's rows.
// Pass 2: recompute y (x re-read hits L1/L2) and write y * (1/segsum).
// y[j] = sum_k x[k] * W[j*4+k]   (nn.Linear: y = x @ W^T, W row-major [4,4])

#define BLOCK 256

__global__ __launch_bounds__(BLOCK)
void seg_norm_kernel(const float4* __restrict__ x,
                     const int*    __restrict__ slices,
                     const float*  __restrict__ W,
                     float4*       __restrict__ out)
{
    const int s  = blockIdx.x;
    const int lo = slices[s];
    const int hi = slices[s + 1];

    // Broadcast the 4x4 weight into registers (uniform across all threads).
    float w[16];
#pragma unroll
    for (int i = 0; i < 16; ++i) w[i] = __ldg(&W[i]);

    __shared__ float red[BLOCK / 32];
    __shared__ float s_inv;

    float local = 0.0f;
    for (int r = lo + (int)threadIdx.x; r < hi; r += BLOCK) {
        float4 v = x[r];
        float y0 = v.x * w[0]  + v.y * w[1]  + v.z * w[2]  + v.w * w[3];
        float y1 = v.x * w[4]  + v.y * w[5]  + v.z * w[6]  + v.w * w[7];
        float y2 = v.x * w[8]  + v.y * w[9]  + v.z * w[10] + v.w * w[11];
        float y3 = v.x * w[12] + v.y * w[13] + v.z * w[14] + v.w * w[15];
        local += fabsf(y0) + fabsf(y1) + fabsf(y2) + fabsf(y3);
    }

    // Warp reduce
#pragma unroll
    for (int o = 16; o > 0; o >>= 1)
        local += __shfl_down_sync(0xFFFFFFFFu, local, o);

    const int lane = threadIdx.x & 31;
    const int warp = threadIdx.x >> 5;
    if (lane == 0) red[warp] = local;
    __syncthreads();

    if (threadIdx.x == 0) {
        float t = 0.0f;
#pragma unroll
        for (int i = 0; i < BLOCK / 32; ++i) t += red[i];
        s_inv = 1.0f / t;   // empty segment -> inf, but then no rows are written
    }
    __syncthreads();
    const float inv = s_inv;

    for (int r = lo + (int)threadIdx.x; r < hi; r += BLOCK) {
        float4 v = x[r];   // L1/L2 hit (just read in pass 1)
        float4 o;
        o.x = (v.x * w[0]  + v.y * w[1]  + v.z * w[2]  + v.w * w[3])  * inv;
        o.y = (v.x * w[4]  + v.y * w[5]  + v.z * w[6]  + v.w * w[7])  * inv;
        o.z = (v.x * w[8]  + v.y * w[9]  + v.z * w[10] + v.w * w[11]) * inv;
        o.w = (v.x * w[12] + v.y * w[13] + v.z * w[14] + v.w * w[15]) * inv;
        out[r] = o;
    }
}

extern "C" void kernel_launch(void* const* d_in, const int* in_sizes, int n_in,
                              void* d_out, int out_size)
{
    const float4* x      = (const float4*)d_in[0];   // [N_ROWS, 4] fp32
    const int*    slices = (const int*)d_in[1];      // [4097] int32
    const float*  W      = (const float*)d_in[2];    // [4, 4] fp32
    float4*       out    = (float4*)d_out;           // [N_ROWS, 4] fp32

    const int n_segments = in_sizes[1] - 1;          // 4096
    seg_norm_kernel<<<n_segments, BLOCK>>>(x, slices, W, out);
}